// round 2
// baseline (speedup 1.0000x reference)
#include <cuda_runtime.h>
#include <cstdint>

// Problem constants
#define B_  8
#define L_  1024
#define D_  1024
#define H_  16
#define DH_ 64
#define HG_ 8
#define M_  (B_*L_)   // 8192

// Scratch (device globals: allocation-free rule)
__device__ float g_k[(size_t)M_ * D_];
__device__ float g_v[(size_t)M_ * D_];
__device__ float g_q[(size_t)M_ * D_];
__device__ float g_ctx[(size_t)M_ * D_];
__device__ unsigned char g_mask[(size_t)B_ * L_ * L_];
__device__ unsigned char g_amask[(size_t)B_ * L_];
__device__ int g_mask_dtype;   // 0 = uint8/bool, 1 = int32, 2 = float32

// ---------------------------------------------------------------------------
// Mask dtype detection: scan first 4096 words of the mask buffer.
//  - any byte >= 2 anywhere            -> float32 (1.0f = 00 00 80 3F)
//  - nonzero byte at positions 1..3    -> uint8  (bools packed per byte)
//  - else                              -> int32  (words are 0 or 1)
// ---------------------------------------------------------------------------
__global__ void detect_mask_dtype(const unsigned int* __restrict__ m)
{
    if (threadIdx.x != 0 || blockIdx.x != 0) return;
    bool bigbyte = false, hibyte = false;
    for (int i = 0; i < 4096; i++) {
        unsigned int w = m[i];
        if (w & 0xFEFEFEFEu) bigbyte = true;   // some byte >= 2
        if (w & 0xFFFFFF00u) hibyte  = true;   // nonzero above byte 0
    }
    g_mask_dtype = bigbyte ? 2 : (hibyte ? 0 : 1);
}

__global__ void convert_mask(const void* __restrict__ src,
                             unsigned char* __restrict__ dst, int n)
{
    int i = blockIdx.x * blockDim.x + threadIdx.x;
    if (i >= n) return;
    const int t = g_mask_dtype;
    unsigned char v;
    if (t == 0)      v = ((const unsigned char*)src)[i] != 0;
    else if (t == 1) v = ((const int*)src)[i] != 0;
    else             v = ((const float*)src)[i] != 0.0f;
    dst[i] = v;
}

// ---------------------------------------------------------------------------
// SGEMM: C[M,N] = scale * (A[M,K] @ W[N,K]^T + bias[N])
// M=8192, N=1024, K=1024. 128x128 tile, BK=8, 256 threads, 8x8 per thread.
// ---------------------------------------------------------------------------
__global__ __launch_bounds__(256) void gemm_atb_kernel(
    const float* __restrict__ A, const float* __restrict__ W,
    const float* __restrict__ bias, float* __restrict__ C, float scale)
{
    const int N = 1024, K = 1024;
    __shared__ float As[8][128];
    __shared__ float Ws[8][128];

    const int tid  = threadIdx.x;
    const int brow = blockIdx.y * 128;
    const int bcol = blockIdx.x * 128;
    const int ty   = tid >> 4;      // 0..15
    const int tx   = tid & 15;      // 0..15

    const int lrow = tid >> 1;          // 0..127
    const int lk4  = (tid & 1) * 4;     // 0 or 4

    const float* Aptr = A + (size_t)(brow + lrow) * K + lk4;
    const float* Wptr = W + (size_t)(bcol + lrow) * K + lk4;

    float acc[8][8];
    #pragma unroll
    for (int i = 0; i < 8; i++)
        #pragma unroll
        for (int j = 0; j < 8; j++) acc[i][j] = 0.0f;

    for (int k0 = 0; k0 < K; k0 += 8) {
        float4 a4 = *(const float4*)(Aptr + k0);
        float4 w4 = *(const float4*)(Wptr + k0);
        As[lk4 + 0][lrow] = a4.x; As[lk4 + 1][lrow] = a4.y;
        As[lk4 + 2][lrow] = a4.z; As[lk4 + 3][lrow] = a4.w;
        Ws[lk4 + 0][lrow] = w4.x; Ws[lk4 + 1][lrow] = w4.y;
        Ws[lk4 + 2][lrow] = w4.z; Ws[lk4 + 3][lrow] = w4.w;
        __syncthreads();

        #pragma unroll
        for (int kk = 0; kk < 8; kk++) {
            float a[8], w[8];
            float4 av0 = *(const float4*)&As[kk][ty * 8];
            float4 av1 = *(const float4*)&As[kk][ty * 8 + 4];
            float4 wv0 = *(const float4*)&Ws[kk][tx * 8];
            float4 wv1 = *(const float4*)&Ws[kk][tx * 8 + 4];
            a[0]=av0.x; a[1]=av0.y; a[2]=av0.z; a[3]=av0.w;
            a[4]=av1.x; a[5]=av1.y; a[6]=av1.z; a[7]=av1.w;
            w[0]=wv0.x; w[1]=wv0.y; w[2]=wv0.z; w[3]=wv0.w;
            w[4]=wv1.x; w[5]=wv1.y; w[6]=wv1.z; w[7]=wv1.w;
            #pragma unroll
            for (int i = 0; i < 8; i++)
                #pragma unroll
                for (int j = 0; j < 8; j++)
                    acc[i][j] = fmaf(a[i], w[j], acc[i][j]);
        }
        __syncthreads();
    }

    #pragma unroll
    for (int i = 0; i < 8; i++) {
        const int row = brow + ty * 8 + i;
        #pragma unroll
        for (int j4 = 0; j4 < 8; j4 += 4) {
            const int col = bcol + tx * 8 + j4;
            float4 o;
            o.x = scale * (acc[i][j4 + 0] + bias[col + 0]);
            o.y = scale * (acc[i][j4 + 1] + bias[col + 1]);
            o.z = scale * (acc[i][j4 + 2] + bias[col + 2]);
            o.w = scale * (acc[i][j4 + 3] + bias[col + 3]);
            *(float4*)&C[(size_t)row * N + col] = o;
        }
    }
}

// ---------------------------------------------------------------------------
// Flash attention (fp32). Grid: (qblock=16, b*h=128), 256 threads.
// 64-query block, 16 key tiles of 64. Online softmax.
// Global heads (h<8): mask[b,q,k]. Local heads (h>=8): additional_mask[b,k].
// Head 0 additionally writes raw (pre-mask) scores to top_score.
// Q was pre-scaled by 0.125 in its projection.
// ---------------------------------------------------------------------------
#define QS(d,i) Qs[(d)*64 + (i)]
#define KS(d,j) Ks[(d)*64 + (j)]
#define VS(j,d) Vs[(j)*64 + (d)]
#define PS(i,j) Ps[(i)*68 + (j)]

#define ATTN_SMEM (((3*64*64) + 64*68) * 4 + 64*64)

__global__ __launch_bounds__(256) void attn_kernel(
    const float* __restrict__ Qb, const float* __restrict__ Kb,
    const float* __restrict__ Vb,
    const unsigned char* __restrict__ mask,
    const unsigned char* __restrict__ amask,
    float* __restrict__ ctx, float* __restrict__ top)
{
    extern __shared__ char smem[];
    float* Qs = (float*)smem;            // [64][64] transposed: Qs[d][i]
    float* Ks = Qs + 64 * 64;            // [64][64] transposed: Ks[d][j]
    float* Vs = Ks + 64 * 64;            // [64][64] direct:     Vs[j][d]
    float* Ps = Vs + 64 * 64;            // [64][68]
    unsigned char* Msk = (unsigned char*)(Ps + 64 * 68);  // [64][64]

    const int tid = threadIdx.x;
    const int b   = blockIdx.y >> 4;
    const int h   = blockIdx.y & 15;
    const int q0  = blockIdx.x * 64;
    const int ty  = tid >> 4;   // row group 0..15
    const int tx  = tid & 15;   // col group 0..15

    // Load Q block (transposed into smem)
    {
        const int dseg = (tid & 15) * 4;
        #pragma unroll
        for (int it = 0; it < 4; it++) {
            const int i = (tid >> 4) + it * 16;
            float4 q4 = *(const float4*)&Qb[((size_t)(b * L_ + q0 + i)) * D_ + h * DH_ + dseg];
            QS(dseg + 0, i) = q4.x; QS(dseg + 1, i) = q4.y;
            QS(dseg + 2, i) = q4.z; QS(dseg + 3, i) = q4.w;
        }
    }

    float acc[4][4];
    float mrow[4], lrow[4];
    #pragma unroll
    for (int r = 0; r < 4; r++) {
        mrow[r] = -1e30f; lrow[r] = 0.0f;
        #pragma unroll
        for (int c = 0; c < 4; c++) acc[r][c] = 0.0f;
    }

    for (int k0 = 0; k0 < L_; k0 += 64) {
        __syncthreads();   // protect Ks/Vs/Ps/Msk reuse from previous iteration

        // Load K (transposed), V (direct), mask tile
        {
            const int dseg = (tid & 15) * 4;
            #pragma unroll
            for (int it = 0; it < 4; it++) {
                const int j = (tid >> 4) + it * 16;
                const size_t base = ((size_t)(b * L_ + k0 + j)) * D_ + h * DH_ + dseg;
                float4 k4 = *(const float4*)&Kb[base];
                KS(dseg + 0, j) = k4.x; KS(dseg + 1, j) = k4.y;
                KS(dseg + 2, j) = k4.z; KS(dseg + 3, j) = k4.w;
                float4 v4 = *(const float4*)&Vb[base];
                *(float4*)&VS(j, dseg) = v4;
            }
            if (h < HG_) {
                const int row = tid >> 2;
                const int seg = (tid & 3) * 16;
                *(uint4*)&Msk[row * 64 + seg] =
                    *(const uint4*)&mask[(size_t)b * L_ * L_ + (size_t)(q0 + row) * L_ + k0 + seg];
            }
        }
        __syncthreads();

        // S = Q @ K^T  (Q already scaled)
        float s[4][4];
        #pragma unroll
        for (int r = 0; r < 4; r++)
            #pragma unroll
            for (int c = 0; c < 4; c++) s[r][c] = 0.0f;

        #pragma unroll 8
        for (int d = 0; d < 64; d++) {
            float4 qv = *(const float4*)&QS(d, ty * 4);
            float4 kv = *(const float4*)&KS(d, tx * 4);
            float qa[4] = {qv.x, qv.y, qv.z, qv.w};
            float ka[4] = {kv.x, kv.y, kv.z, kv.w};
            #pragma unroll
            for (int r = 0; r < 4; r++)
                #pragma unroll
                for (int c = 0; c < 4; c++)
                    s[r][c] = fmaf(qa[r], ka[c], s[r][c]);
        }

        // head 0: raw scores out (pre-mask)
        if (h == 0) {
            #pragma unroll
            for (int r = 0; r < 4; r++) {
                *(float4*)&top[(size_t)b * L_ * L_ + (size_t)(q0 + ty * 4 + r) * L_ + k0 + tx * 4] =
                    make_float4(s[r][0], s[r][1], s[r][2], s[r][3]);
            }
        }

        // Masking
        if (h < HG_) {
            #pragma unroll
            for (int r = 0; r < 4; r++)
                #pragma unroll
                for (int c = 0; c < 4; c++)
                    if (Msk[(ty * 4 + r) * 64 + tx * 4 + c]) s[r][c] = -1e18f;
        } else {
            unsigned char am[4];
            #pragma unroll
            for (int c = 0; c < 4; c++) am[c] = amask[(size_t)b * L_ + k0 + tx * 4 + c];
            #pragma unroll
            for (int r = 0; r < 4; r++)
                #pragma unroll
                for (int c = 0; c < 4; c++)
                    if (am[c]) s[r][c] = -1e18f;
        }

        // Online softmax update
        #pragma unroll
        for (int r = 0; r < 4; r++) {
            float m = fmaxf(fmaxf(s[r][0], s[r][1]), fmaxf(s[r][2], s[r][3]));
            #pragma unroll
            for (int off = 8; off > 0; off >>= 1)
                m = fmaxf(m, __shfl_xor_sync(0xffffffffu, m, off));
            const float mn   = fmaxf(mrow[r], m);
            const float corr = __expf(mrow[r] - mn);
            mrow[r] = mn;
            float psum = 0.0f;
            #pragma unroll
            for (int c = 0; c < 4; c++) {
                float p = __expf(s[r][c] - mn);
                s[r][c] = p;
                psum += p;
            }
            #pragma unroll
            for (int off = 8; off > 0; off >>= 1)
                psum += __shfl_xor_sync(0xffffffffu, psum, off);
            lrow[r] = lrow[r] * corr + psum;
            #pragma unroll
            for (int c = 0; c < 4; c++) acc[r][c] *= corr;
            *(float4*)&PS(ty * 4 + r, tx * 4) = make_float4(s[r][0], s[r][1], s[r][2], s[r][3]);
        }
        __syncthreads();

        // acc += P @ V
        #pragma unroll 8
        for (int j = 0; j < 64; j++) {
            float4 v4 = *(const float4*)&VS(j, tx * 4);
            float va[4] = {v4.x, v4.y, v4.z, v4.w};
            #pragma unroll
            for (int r = 0; r < 4; r++) {
                const float p = PS(ty * 4 + r, j);
                #pragma unroll
                for (int c = 0; c < 4; c++)
                    acc[r][c] = fmaf(p, va[c], acc[r][c]);
            }
        }
    }

    // Epilogue: ctx = acc / l
    #pragma unroll
    for (int r = 0; r < 4; r++) {
        const float inv = 1.0f / lrow[r];
        *(float4*)&ctx[((size_t)(b * L_ + q0 + ty * 4 + r)) * D_ + h * DH_ + tx * 4] =
            make_float4(acc[r][0] * inv, acc[r][1] * inv, acc[r][2] * inv, acc[r][3] * inv);
    }
}

// ---------------------------------------------------------------------------
// Launch
// ---------------------------------------------------------------------------
extern "C" void kernel_launch(void* const* d_in, const int* in_sizes, int n_in,
                              void* d_out, int out_size)
{
    const float* key   = (const float*)d_in[0];
    const float* value = (const float*)d_in[1];
    const float* query = (const float*)d_in[2];
    const void*  mask_raw  = d_in[3];
    const void*  amask_raw = d_in[4];
    const float* Wk = (const float*)d_in[5];
    const float* bk = (const float*)d_in[6];
    const float* Wv = (const float*)d_in[7];
    const float* bv = (const float*)d_in[8];
    const float* Wq = (const float*)d_in[9];
    const float* bq = (const float*)d_in[10];
    const float* Wo = (const float*)d_in[11];
    const float* bo = (const float*)d_in[12];

    float* out = (float*)d_out;
    float* top = out + (size_t)M_ * D_;

    float *kbuf, *vbuf, *qbuf, *ctxbuf;
    unsigned char *maskbuf, *amaskbuf;
    cudaGetSymbolAddress((void**)&kbuf, g_k);
    cudaGetSymbolAddress((void**)&vbuf, g_v);
    cudaGetSymbolAddress((void**)&qbuf, g_q);
    cudaGetSymbolAddress((void**)&ctxbuf, g_ctx);
    cudaGetSymbolAddress((void**)&maskbuf, g_mask);
    cudaGetSymbolAddress((void**)&amaskbuf, g_amask);

    cudaFuncSetAttribute(attn_kernel, cudaFuncAttributeMaxDynamicSharedMemorySize, ATTN_SMEM);

    // Normalize masks to uint8 (dtype auto-detected on device)
    detect_mask_dtype<<<1, 32>>>((const unsigned int*)mask_raw);
    const int nmask = B_ * L_ * L_;
    convert_mask<<<(nmask + 255) / 256, 256>>>(mask_raw, maskbuf, nmask);
    convert_mask<<<(B_ * L_ + 255) / 256, 256>>>(amask_raw, amaskbuf, B_ * L_);

    dim3 gg(D_ / 128, M_ / 128);  // (8, 64)
    gemm_atb_kernel<<<gg, 256>>>(key,   Wk, bk, kbuf, 1.0f);
    gemm_atb_kernel<<<gg, 256>>>(value, Wv, bv, vbuf, 1.0f);
    gemm_atb_kernel<<<gg, 256>>>(query, Wq, bq, qbuf, 0.125f);  // 1/sqrt(64)

    attn_kernel<<<dim3(16, B_ * H_), 256, ATTN_SMEM>>>(qbuf, kbuf, vbuf, maskbuf, amaskbuf, ctxbuf, top);

    gemm_atb_kernel<<<gg, 256>>>(ctxbuf, Wo, bo, out, 1.0f);
}

// round 4
// speedup vs baseline: 1.5878x; 1.5878x over previous
#include <cuda_runtime.h>
#include <cuda_bf16.h>
#include <cstdint>

// Problem constants
#define B_  8
#define L_  1024
#define D_  1024
#define H_  16
#define DH_ 64
#define HG_ 8
#define M_  (B_*L_)   // 8192

// Scratch (device globals: allocation-free rule)
__device__ float g_k[(size_t)M_ * D_];
__device__ float g_v[(size_t)M_ * D_];
__device__ float g_q[(size_t)M_ * D_];
__device__ float g_ctx[(size_t)M_ * D_];
__device__ unsigned char g_mask[(size_t)B_ * L_ * L_];
__device__ unsigned char g_amask[(size_t)B_ * L_];
__device__ int g_mask_dtype;   // 0 = uint8/bool, 1 = int32, 2 = float32

// ---------------------------------------------------------------------------
// Helpers
// ---------------------------------------------------------------------------
__device__ __forceinline__ uint32_t smem_u32(const void* p) {
    uint32_t a;
    asm("{ .reg .u64 t; cvta.to.shared.u64 t, %1; cvt.u32.u64 %0, t; }" : "=r"(a) : "l"(p));
    return a;
}

__device__ __forceinline__ void ldm4(uint32_t* r, uint32_t addr) {
    asm volatile("ldmatrix.sync.aligned.m8n8.x4.shared.b16 {%0,%1,%2,%3}, [%4];"
                 : "=r"(r[0]), "=r"(r[1]), "=r"(r[2]), "=r"(r[3]) : "r"(addr));
}

__device__ __forceinline__ void mma16816(float* d, const uint32_t* a,
                                         uint32_t b0, uint32_t b1) {
    asm volatile("mma.sync.aligned.m16n8k16.row.col.f32.bf16.bf16.f32 "
                 "{%0,%1,%2,%3}, {%4,%5,%6,%7}, {%8,%9}, {%0,%1,%2,%3};"
                 : "+f"(d[0]), "+f"(d[1]), "+f"(d[2]), "+f"(d[3])
                 : "r"(a[0]), "r"(a[1]), "r"(a[2]), "r"(a[3]), "r"(b0), "r"(b1));
}

__device__ __forceinline__ uint32_t pack_bf16x2(float x, float y) {
    __nv_bfloat162 v = __floats2bfloat162_rn(x, y);
    return *(uint32_t*)&v;
}

// ---------------------------------------------------------------------------
// Mask dtype detection + conversion
// ---------------------------------------------------------------------------
__global__ void detect_mask_dtype(const unsigned int* __restrict__ m)
{
    if (threadIdx.x != 0 || blockIdx.x != 0) return;
    bool bigbyte = false, hibyte = false;
    for (int i = 0; i < 4096; i++) {
        unsigned int w = m[i];
        if (w & 0xFEFEFEFEu) bigbyte = true;
        if (w & 0xFFFFFF00u) hibyte  = true;
    }
    g_mask_dtype = bigbyte ? 2 : (hibyte ? 0 : 1);
}

__global__ void convert_mask(const void* __restrict__ src,
                             unsigned char* __restrict__ dst, int n)
{
    int i = blockIdx.x * blockDim.x + threadIdx.x;
    if (i >= n) return;
    const int t = g_mask_dtype;
    unsigned char v;
    if (t == 0)      v = ((const unsigned char*)src)[i] != 0;
    else if (t == 1) v = ((const int*)src)[i] != 0;
    else             v = ((const float*)src)[i] != 0.0f;
    dst[i] = v;
}

// ---------------------------------------------------------------------------
// bf16x3 mma.sync GEMM: C[M,N] = scale * (A[M,K] @ W[N,K]^T + bias[N])
// CTA tile 128x128, BK=64, 16 stages. 8 warps, warp tile 32(M)x64(N).
// A,W split into bf16 hi+lo; 3 passes: Ah*Wh + Ah*Wl + Al*Wh (fp32 acc).
// Smem rows padded to 72 bf16 (144B) -> conflict-free ldmatrix.
// ---------------------------------------------------------------------------
#define SROW 144                       // bytes per smem row (72 bf16)
#define AH_OFF 0
#define AL_OFF (128*SROW)              // 18432
#define BH_OFF (2*128*SROW)
#define BL_OFF (3*128*SROW)
#define GEMM_SMEM (4*128*SROW)         // 73728

__global__ __launch_bounds__(256, 2)
void gemm_mma_kernel(const float* __restrict__ A, const float* __restrict__ W,
                     const float* __restrict__ bias, float* __restrict__ C, float scale)
{
    extern __shared__ char sm[];
    const uint32_t sb = smem_u32(sm);

    const int tid  = threadIdx.x;
    const int wid  = tid >> 5;
    const int lane = tid & 31;
    const int m0   = blockIdx.y * 128;
    const int n0   = blockIdx.x * 128;
    const int wm   = wid & 3;          // 0..3  -> M offset wm*32
    const int wn   = wid >> 2;         // 0..1  -> N offset wn*64

    float acc[2][8][4];
    #pragma unroll
    for (int mf = 0; mf < 2; mf++)
        #pragma unroll
        for (int nf = 0; nf < 8; nf++)
            #pragma unroll
            for (int c = 0; c < 4; c++) acc[mf][nf][c] = 0.0f;

    const int lrow = tid >> 4;         // 0..15 (row group for loads)
    const int lc4  = tid & 15;         // float4 index within 64-col stage

    // ldmatrix base offsets (byte) within a tile
    const int a_ld_row = wm * 32 + (lane & 15);
    const int b_ld_row = wn * 64 + (lane & 15);
    const int ld_khalf = (lane >> 4) * 8;   // 0 or 8 (bf16 elems)

    for (int s = 0; s < 16; s++) {
        const int k0 = s * 64;
        if (s) __syncthreads();

        // Load 128x64 fp32 tiles of A and W, split to bf16 hi/lo, store smem.
        #pragma unroll
        for (int i = 0; i < 8; i++) {
            const int row = lrow + i * 16;
            const uint32_t soff = (uint32_t)(row * SROW + lc4 * 8);

            float4 a = *(const float4*)&A[(size_t)(m0 + row) * 1024 + k0 + lc4 * 4];
            uint32_t h0 = pack_bf16x2(a.x, a.y);
            uint32_t h1 = pack_bf16x2(a.z, a.w);
            float lx = a.x - __uint_as_float(h0 << 16);
            float ly = a.y - __uint_as_float(h0 & 0xFFFF0000u);
            float lz = a.z - __uint_as_float(h1 << 16);
            float lw = a.w - __uint_as_float(h1 & 0xFFFF0000u);
            *(uint2*)(sm + AH_OFF + soff) = make_uint2(h0, h1);
            *(uint2*)(sm + AL_OFF + soff) = make_uint2(pack_bf16x2(lx, ly), pack_bf16x2(lz, lw));

            float4 b = *(const float4*)&W[(size_t)(n0 + row) * 1024 + k0 + lc4 * 4];
            h0 = pack_bf16x2(b.x, b.y);
            h1 = pack_bf16x2(b.z, b.w);
            lx = b.x - __uint_as_float(h0 << 16);
            ly = b.y - __uint_as_float(h0 & 0xFFFF0000u);
            lz = b.z - __uint_as_float(h1 << 16);
            lw = b.w - __uint_as_float(h1 & 0xFFFF0000u);
            *(uint2*)(sm + BH_OFF + soff) = make_uint2(h0, h1);
            *(uint2*)(sm + BL_OFF + soff) = make_uint2(pack_bf16x2(lx, ly), pack_bf16x2(lz, lw));
        }
        __syncthreads();

        // MMA over 4 k16 steps
        #pragma unroll
        for (int kk = 0; kk < 4; kk++) {
            const uint32_t acol = (uint32_t)((kk * 16 + ld_khalf) * 2);
            uint32_t ah[2][4], al[2][4];
            ldm4(ah[0], sb + AH_OFF + (uint32_t)(a_ld_row * SROW)        + acol);
            ldm4(ah[1], sb + AH_OFF + (uint32_t)((a_ld_row + 16) * SROW) + acol);
            ldm4(al[0], sb + AL_OFF + (uint32_t)(a_ld_row * SROW)        + acol);
            ldm4(al[1], sb + AL_OFF + (uint32_t)((a_ld_row + 16) * SROW) + acol);

            #pragma unroll
            for (int g = 0; g < 4; g++) {
                const uint32_t boff = (uint32_t)((b_ld_row + g * 16) * SROW) + acol;
                uint32_t bh[4], bl[4];
                ldm4(bh, sb + BH_OFF + boff);
                ldm4(bl, sb + BL_OFF + boff);
                // n8 frag 2g:   {r0, r2};  n8 frag 2g+1: {r1, r3}
                #pragma unroll
                for (int mf = 0; mf < 2; mf++) {
                    mma16816(acc[mf][2 * g],     ah[mf], bh[0], bh[2]);
                    mma16816(acc[mf][2 * g + 1], ah[mf], bh[1], bh[3]);
                    mma16816(acc[mf][2 * g],     ah[mf], bl[0], bl[2]);
                    mma16816(acc[mf][2 * g + 1], ah[mf], bl[1], bl[3]);
                    mma16816(acc[mf][2 * g],     al[mf], bh[0], bh[2]);
                    mma16816(acc[mf][2 * g + 1], al[mf], bh[1], bh[3]);
                }
            }
        }
    }

    // Epilogue
    const int gq = lane >> 2;
    const int t4 = lane & 3;
    #pragma unroll
    for (int mf = 0; mf < 2; mf++) {
        const int row = m0 + wm * 32 + mf * 16 + gq;
        #pragma unroll
        for (int nf = 0; nf < 8; nf++) {
            const int col = n0 + wn * 64 + nf * 8 + t4 * 2;
            const float b0 = bias[col], b1 = bias[col + 1];
            *(float2*)&C[(size_t)row * 1024 + col] =
                make_float2(scale * (acc[mf][nf][0] + b0), scale * (acc[mf][nf][1] + b1));
            *(float2*)&C[(size_t)(row + 8) * 1024 + col] =
                make_float2(scale * (acc[mf][nf][2] + b0), scale * (acc[mf][nf][3] + b1));
        }
    }
}

// ---------------------------------------------------------------------------
// Flash attention (fp32). Grid: (qblock=16, b*h=128), 256 threads.
// ---------------------------------------------------------------------------
#define QS(d,i) Qs[(d)*64 + (i)]
#define KS(d,j) Ks[(d)*64 + (j)]
#define VS(j,d) Vs[(j)*64 + (d)]
#define PS(i,j) Ps[(i)*68 + (j)]

#define ATTN_SMEM (((3*64*64) + 64*68) * 4 + 64*64)

__global__ __launch_bounds__(256) void attn_kernel(
    const float* __restrict__ Qb, const float* __restrict__ Kb,
    const float* __restrict__ Vb,
    const unsigned char* __restrict__ mask,
    const unsigned char* __restrict__ amask,
    float* __restrict__ ctx, float* __restrict__ top)
{
    extern __shared__ char smem[];
    float* Qs = (float*)smem;
    float* Ks = Qs + 64 * 64;
    float* Vs = Ks + 64 * 64;
    float* Ps = Vs + 64 * 64;
    unsigned char* Msk = (unsigned char*)(Ps + 64 * 68);

    const int tid = threadIdx.x;
    const int b   = blockIdx.y >> 4;
    const int h   = blockIdx.y & 15;
    const int q0  = blockIdx.x * 64;
    const int ty  = tid >> 4;
    const int tx  = tid & 15;

    {
        const int dseg = (tid & 15) * 4;
        #pragma unroll
        for (int it = 0; it < 4; it++) {
            const int i = (tid >> 4) + it * 16;
            float4 q4 = *(const float4*)&Qb[((size_t)(b * L_ + q0 + i)) * D_ + h * DH_ + dseg];
            QS(dseg + 0, i) = q4.x; QS(dseg + 1, i) = q4.y;
            QS(dseg + 2, i) = q4.z; QS(dseg + 3, i) = q4.w;
        }
    }

    float acc[4][4];
    float mrow[4], lrow[4];
    #pragma unroll
    for (int r = 0; r < 4; r++) {
        mrow[r] = -1e30f; lrow[r] = 0.0f;
        #pragma unroll
        for (int c = 0; c < 4; c++) acc[r][c] = 0.0f;
    }

    for (int k0 = 0; k0 < L_; k0 += 64) {
        __syncthreads();

        {
            const int dseg = (tid & 15) * 4;
            #pragma unroll
            for (int it = 0; it < 4; it++) {
                const int j = (tid >> 4) + it * 16;
                const size_t base = ((size_t)(b * L_ + k0 + j)) * D_ + h * DH_ + dseg;
                float4 k4 = *(const float4*)&Kb[base];
                KS(dseg + 0, j) = k4.x; KS(dseg + 1, j) = k4.y;
                KS(dseg + 2, j) = k4.z; KS(dseg + 3, j) = k4.w;
                float4 v4 = *(const float4*)&Vb[base];
                *(float4*)&VS(j, dseg) = v4;
            }
            if (h < HG_) {
                const int row = tid >> 2;
                const int seg = (tid & 3) * 16;
                *(uint4*)&Msk[row * 64 + seg] =
                    *(const uint4*)&mask[(size_t)b * L_ * L_ + (size_t)(q0 + row) * L_ + k0 + seg];
            }
        }
        __syncthreads();

        float s[4][4];
        #pragma unroll
        for (int r = 0; r < 4; r++)
            #pragma unroll
            for (int c = 0; c < 4; c++) s[r][c] = 0.0f;

        #pragma unroll 8
        for (int d = 0; d < 64; d++) {
            float4 qv = *(const float4*)&QS(d, ty * 4);
            float4 kv = *(const float4*)&KS(d, tx * 4);
            float qa[4] = {qv.x, qv.y, qv.z, qv.w};
            float ka[4] = {kv.x, kv.y, kv.z, kv.w};
            #pragma unroll
            for (int r = 0; r < 4; r++)
                #pragma unroll
                for (int c = 0; c < 4; c++)
                    s[r][c] = fmaf(qa[r], ka[c], s[r][c]);
        }

        if (h == 0) {
            #pragma unroll
            for (int r = 0; r < 4; r++) {
                *(float4*)&top[(size_t)b * L_ * L_ + (size_t)(q0 + ty * 4 + r) * L_ + k0 + tx * 4] =
                    make_float4(s[r][0], s[r][1], s[r][2], s[r][3]);
            }
        }

        if (h < HG_) {
            #pragma unroll
            for (int r = 0; r < 4; r++)
                #pragma unroll
                for (int c = 0; c < 4; c++)
                    if (Msk[(ty * 4 + r) * 64 + tx * 4 + c]) s[r][c] = -1e18f;
        } else {
            unsigned char am[4];
            #pragma unroll
            for (int c = 0; c < 4; c++) am[c] = amask[(size_t)b * L_ + k0 + tx * 4 + c];
            #pragma unroll
            for (int r = 0; r < 4; r++)
                #pragma unroll
                for (int c = 0; c < 4; c++)
                    if (am[c]) s[r][c] = -1e18f;
        }

        #pragma unroll
        for (int r = 0; r < 4; r++) {
            float m = fmaxf(fmaxf(s[r][0], s[r][1]), fmaxf(s[r][2], s[r][3]));
            #pragma unroll
            for (int off = 8; off > 0; off >>= 1)
                m = fmaxf(m, __shfl_xor_sync(0xffffffffu, m, off));
            const float mn   = fmaxf(mrow[r], m);
            const float corr = __expf(mrow[r] - mn);
            mrow[r] = mn;
            float psum = 0.0f;
            #pragma unroll
            for (int c = 0; c < 4; c++) {
                float p = __expf(s[r][c] - mn);
                s[r][c] = p;
                psum += p;
            }
            #pragma unroll
            for (int off = 8; off > 0; off >>= 1)
                psum += __shfl_xor_sync(0xffffffffu, psum, off);
            lrow[r] = lrow[r] * corr + psum;
            #pragma unroll
            for (int c = 0; c < 4; c++) acc[r][c] *= corr;
            *(float4*)&PS(ty * 4 + r, tx * 4) = make_float4(s[r][0], s[r][1], s[r][2], s[r][3]);
        }
        __syncthreads();

        #pragma unroll 8
        for (int j = 0; j < 64; j++) {
            float4 v4 = *(const float4*)&VS(j, tx * 4);
            float va[4] = {v4.x, v4.y, v4.z, v4.w};
            #pragma unroll
            for (int r = 0; r < 4; r++) {
                const float p = PS(ty * 4 + r, j);
                #pragma unroll
                for (int c = 0; c < 4; c++)
                    acc[r][c] = fmaf(p, va[c], acc[r][c]);
            }
        }
    }

    #pragma unroll
    for (int r = 0; r < 4; r++) {
        const float inv = 1.0f / lrow[r];
        *(float4*)&ctx[((size_t)(b * L_ + q0 + ty * 4 + r)) * D_ + h * DH_ + tx * 4] =
            make_float4(acc[r][0] * inv, acc[r][1] * inv, acc[r][2] * inv, acc[r][3] * inv);
    }
}

// ---------------------------------------------------------------------------
// Launch
// ---------------------------------------------------------------------------
extern "C" void kernel_launch(void* const* d_in, const int* in_sizes, int n_in,
                              void* d_out, int out_size)
{
    const float* key   = (const float*)d_in[0];
    const float* value = (const float*)d_in[1];
    const float* query = (const float*)d_in[2];
    const void*  mask_raw  = d_in[3];
    const void*  amask_raw = d_in[4];
    const float* Wk = (const float*)d_in[5];
    const float* bk = (const float*)d_in[6];
    const float* Wv = (const float*)d_in[7];
    const float* bv = (const float*)d_in[8];
    const float* Wq = (const float*)d_in[9];
    const float* bq = (const float*)d_in[10];
    const float* Wo = (const float*)d_in[11];
    const float* bo = (const float*)d_in[12];

    float* out = (float*)d_out;
    float* top = out + (size_t)M_ * D_;

    float *kbuf, *vbuf, *qbuf, *ctxbuf;
    unsigned char *maskbuf, *amaskbuf;
    cudaGetSymbolAddress((void**)&kbuf, g_k);
    cudaGetSymbolAddress((void**)&vbuf, g_v);
    cudaGetSymbolAddress((void**)&qbuf, g_q);
    cudaGetSymbolAddress((void**)&ctxbuf, g_ctx);
    cudaGetSymbolAddress((void**)&maskbuf, g_mask);
    cudaGetSymbolAddress((void**)&amaskbuf, g_amask);

    cudaFuncSetAttribute(attn_kernel, cudaFuncAttributeMaxDynamicSharedMemorySize, ATTN_SMEM);
    cudaFuncSetAttribute(gemm_mma_kernel, cudaFuncAttributeMaxDynamicSharedMemorySize, GEMM_SMEM);

    // Normalize masks to uint8 (dtype auto-detected on device)
    detect_mask_dtype<<<1, 32>>>((const unsigned int*)mask_raw);
    const int nmask = B_ * L_ * L_;
    convert_mask<<<(nmask + 255) / 256, 256>>>(mask_raw, maskbuf, nmask);
    convert_mask<<<(B_ * L_ + 255) / 256, 256>>>(amask_raw, amaskbuf, B_ * L_);

    dim3 gg(D_ / 128, M_ / 128);  // (8, 64)
    gemm_mma_kernel<<<gg, 256, GEMM_SMEM>>>(key,   Wk, bk, kbuf, 1.0f);
    gemm_mma_kernel<<<gg, 256, GEMM_SMEM>>>(value, Wv, bv, vbuf, 1.0f);
    gemm_mma_kernel<<<gg, 256, GEMM_SMEM>>>(query, Wq, bq, qbuf, 0.125f);  // 1/sqrt(64)

    attn_kernel<<<dim3(16, B_ * H_), 256, ATTN_SMEM>>>(qbuf, kbuf, vbuf, maskbuf, amaskbuf, ctxbuf, top);

    gemm_mma_kernel<<<gg, 256, GEMM_SMEM>>>(ctxbuf, Wo, bo, out, 1.0f);
}

// round 5
// speedup vs baseline: 2.6523x; 1.6705x over previous
#include <cuda_runtime.h>
#include <cuda_bf16.h>
#include <cstdint>

// Problem constants
#define B_  8
#define L_  1024
#define D_  1024
#define H_  16
#define DH_ 64
#define HG_ 8
#define M_  (B_*L_)   // 8192

// Scratch (device globals: allocation-free rule)
__device__ float g_ctx[(size_t)M_ * D_];
__device__ __nv_bfloat16 g_khi[(size_t)M_ * D_];
__device__ __nv_bfloat16 g_klo[(size_t)M_ * D_];
__device__ __nv_bfloat16 g_vhi[(size_t)M_ * D_];
__device__ __nv_bfloat16 g_vlo[(size_t)M_ * D_];
__device__ __nv_bfloat16 g_qhi[(size_t)M_ * D_];
__device__ __nv_bfloat16 g_qlo[(size_t)M_ * D_];
__device__ unsigned char g_mask[(size_t)B_ * L_ * L_];
__device__ unsigned char g_amask[(size_t)B_ * L_];
__device__ int g_mask_dtype;   // 0 = uint8/bool, 1 = int32, 2 = float32

// ---------------------------------------------------------------------------
// Helpers
// ---------------------------------------------------------------------------
__device__ __forceinline__ uint32_t smem_u32(const void* p) {
    uint32_t a;
    asm("{ .reg .u64 t; cvta.to.shared.u64 t, %1; cvt.u32.u64 %0, t; }" : "=r"(a) : "l"(p));
    return a;
}

__device__ __forceinline__ void ldm4(uint32_t* r, uint32_t addr) {
    asm volatile("ldmatrix.sync.aligned.m8n8.x4.shared.b16 {%0,%1,%2,%3}, [%4];"
                 : "=r"(r[0]), "=r"(r[1]), "=r"(r[2]), "=r"(r[3]) : "r"(addr));
}

__device__ __forceinline__ void ldm4t(uint32_t* r, uint32_t addr) {
    asm volatile("ldmatrix.sync.aligned.m8n8.x4.trans.shared.b16 {%0,%1,%2,%3}, [%4];"
                 : "=r"(r[0]), "=r"(r[1]), "=r"(r[2]), "=r"(r[3]) : "r"(addr));
}

__device__ __forceinline__ void mma16816(float* d, const uint32_t* a,
                                         uint32_t b0, uint32_t b1) {
    asm volatile("mma.sync.aligned.m16n8k16.row.col.f32.bf16.bf16.f32 "
                 "{%0,%1,%2,%3}, {%4,%5,%6,%7}, {%8,%9}, {%0,%1,%2,%3};"
                 : "+f"(d[0]), "+f"(d[1]), "+f"(d[2]), "+f"(d[3])
                 : "r"(a[0]), "r"(a[1]), "r"(a[2]), "r"(a[3]), "r"(b0), "r"(b1));
}

__device__ __forceinline__ uint32_t pack_bf16x2(float x, float y) {
    __nv_bfloat162 v = __floats2bfloat162_rn(x, y);
    return *(uint32_t*)&v;
}

// hi = bf16(x); returns packed hi pair and computes lo pair
__device__ __forceinline__ void split2(float x, float y, uint32_t& hi, uint32_t& lo) {
    hi = pack_bf16x2(x, y);
    float lx = x - __uint_as_float(hi << 16);
    float ly = y - __uint_as_float(hi & 0xFFFF0000u);
    lo = pack_bf16x2(lx, ly);
}

// ---------------------------------------------------------------------------
// Mask dtype detection + conversion
// ---------------------------------------------------------------------------
__global__ void detect_mask_dtype(const unsigned int* __restrict__ m)
{
    if (threadIdx.x != 0 || blockIdx.x != 0) return;
    bool bigbyte = false, hibyte = false;
    for (int i = 0; i < 4096; i++) {
        unsigned int w = m[i];
        if (w & 0xFEFEFEFEu) bigbyte = true;
        if (w & 0xFFFFFF00u) hibyte  = true;
    }
    g_mask_dtype = bigbyte ? 2 : (hibyte ? 0 : 1);
}

__global__ void convert_mask(const void* __restrict__ src,
                             unsigned char* __restrict__ dst, int n)
{
    int i = blockIdx.x * blockDim.x + threadIdx.x;
    if (i >= n) return;
    const int t = g_mask_dtype;
    unsigned char v;
    if (t == 0)      v = ((const unsigned char*)src)[i] != 0;
    else if (t == 1) v = ((const int*)src)[i] != 0;
    else             v = ((const float*)src)[i] != 0.0f;
    dst[i] = v;
}

// ---------------------------------------------------------------------------
// bf16x3 mma.sync GEMM: out = scale * (A[M,K] @ W[N,K]^T + bias[N])
// Optionally writes fp32 C and/or bf16 hi/lo pair (Chi/Clo).
// ---------------------------------------------------------------------------
#define SROW 144                       // bytes per smem row (72 bf16)
#define AH_OFF 0
#define AL_OFF (128*SROW)
#define BH_OFF (2*128*SROW)
#define BL_OFF (3*128*SROW)
#define GEMM_SMEM (4*128*SROW)         // 73728

__global__ __launch_bounds__(256, 2)
void gemm_mma_kernel(const float* __restrict__ A, const float* __restrict__ W,
                     const float* __restrict__ bias, float* __restrict__ C,
                     __nv_bfloat16* __restrict__ Chi, __nv_bfloat16* __restrict__ Clo,
                     float scale)
{
    extern __shared__ char sm[];
    const uint32_t sb = smem_u32(sm);

    const int tid  = threadIdx.x;
    const int wid  = tid >> 5;
    const int lane = tid & 31;
    const int m0   = blockIdx.y * 128;
    const int n0   = blockIdx.x * 128;
    const int wm   = wid & 3;
    const int wn   = wid >> 2;

    float acc[2][8][4];
    #pragma unroll
    for (int mf = 0; mf < 2; mf++)
        #pragma unroll
        for (int nf = 0; nf < 8; nf++)
            #pragma unroll
            for (int c = 0; c < 4; c++) acc[mf][nf][c] = 0.0f;

    const int lrow = tid >> 4;
    const int lc4  = tid & 15;

    const int a_ld_row = wm * 32 + (lane & 15);
    const int b_ld_row = wn * 64 + (lane & 15);
    const int ld_khalf = (lane >> 4) * 8;

    for (int s = 0; s < 16; s++) {
        const int k0 = s * 64;
        if (s) __syncthreads();

        #pragma unroll
        for (int i = 0; i < 8; i++) {
            const int row = lrow + i * 16;
            const uint32_t soff = (uint32_t)(row * SROW + lc4 * 8);

            float4 a = *(const float4*)&A[(size_t)(m0 + row) * 1024 + k0 + lc4 * 4];
            uint32_t h0, l0, h1, l1;
            split2(a.x, a.y, h0, l0);
            split2(a.z, a.w, h1, l1);
            *(uint2*)(sm + AH_OFF + soff) = make_uint2(h0, h1);
            *(uint2*)(sm + AL_OFF + soff) = make_uint2(l0, l1);

            float4 b = *(const float4*)&W[(size_t)(n0 + row) * 1024 + k0 + lc4 * 4];
            split2(b.x, b.y, h0, l0);
            split2(b.z, b.w, h1, l1);
            *(uint2*)(sm + BH_OFF + soff) = make_uint2(h0, h1);
            *(uint2*)(sm + BL_OFF + soff) = make_uint2(l0, l1);
        }
        __syncthreads();

        #pragma unroll
        for (int kk = 0; kk < 4; kk++) {
            const uint32_t acol = (uint32_t)((kk * 16 + ld_khalf) * 2);
            uint32_t ah[2][4], al[2][4];
            ldm4(ah[0], sb + AH_OFF + (uint32_t)(a_ld_row * SROW)        + acol);
            ldm4(ah[1], sb + AH_OFF + (uint32_t)((a_ld_row + 16) * SROW) + acol);
            ldm4(al[0], sb + AL_OFF + (uint32_t)(a_ld_row * SROW)        + acol);
            ldm4(al[1], sb + AL_OFF + (uint32_t)((a_ld_row + 16) * SROW) + acol);

            #pragma unroll
            for (int g = 0; g < 4; g++) {
                const uint32_t boff = (uint32_t)((b_ld_row + g * 16) * SROW) + acol;
                uint32_t bh[4], bl[4];
                ldm4(bh, sb + BH_OFF + boff);
                ldm4(bl, sb + BL_OFF + boff);
                #pragma unroll
                for (int mf = 0; mf < 2; mf++) {
                    mma16816(acc[mf][2 * g],     ah[mf], bh[0], bh[2]);
                    mma16816(acc[mf][2 * g + 1], ah[mf], bh[1], bh[3]);
                    mma16816(acc[mf][2 * g],     ah[mf], bl[0], bl[2]);
                    mma16816(acc[mf][2 * g + 1], ah[mf], bl[1], bl[3]);
                    mma16816(acc[mf][2 * g],     al[mf], bh[0], bh[2]);
                    mma16816(acc[mf][2 * g + 1], al[mf], bh[1], bh[3]);
                }
            }
        }
    }

    // Epilogue
    const int gq = lane >> 2;
    const int t4 = lane & 3;
    #pragma unroll
    for (int mf = 0; mf < 2; mf++) {
        const int row = m0 + wm * 32 + mf * 16 + gq;
        #pragma unroll
        for (int nf = 0; nf < 8; nf++) {
            const int col = n0 + wn * 64 + nf * 8 + t4 * 2;
            const float b0 = bias[col], b1 = bias[col + 1];
            float v0 = scale * (acc[mf][nf][0] + b0);
            float v1 = scale * (acc[mf][nf][1] + b1);
            float v2 = scale * (acc[mf][nf][2] + b0);
            float v3 = scale * (acc[mf][nf][3] + b1);
            if (C) {
                *(float2*)&C[(size_t)row * 1024 + col]       = make_float2(v0, v1);
                *(float2*)&C[(size_t)(row + 8) * 1024 + col] = make_float2(v2, v3);
            }
            if (Chi) {
                uint32_t h, l;
                split2(v0, v1, h, l);
                *(uint32_t*)&Chi[(size_t)row * 1024 + col] = h;
                *(uint32_t*)&Clo[(size_t)row * 1024 + col] = l;
                split2(v2, v3, h, l);
                *(uint32_t*)&Chi[(size_t)(row + 8) * 1024 + col] = h;
                *(uint32_t*)&Clo[(size_t)(row + 8) * 1024 + col] = l;
            }
        }
    }
}

// ---------------------------------------------------------------------------
// Tensor-core flash attention (bf16x3). Grid: (16 qblocks, 128 bh), 128 thr.
// CTA: 64 queries; 4 warps x 16q. Key tiles of 64. Online softmax fp32.
// ---------------------------------------------------------------------------
#define SR 72   // bf16 elems per smem row (144B)

__global__ __launch_bounds__(128, 3) void attn_tc_kernel(
    const __nv_bfloat16* __restrict__ qhi, const __nv_bfloat16* __restrict__ qlo,
    const __nv_bfloat16* __restrict__ khi, const __nv_bfloat16* __restrict__ klo,
    const __nv_bfloat16* __restrict__ vhi, const __nv_bfloat16* __restrict__ vlo,
    const unsigned char* __restrict__ mask, const unsigned char* __restrict__ amask,
    float* __restrict__ ctx, float* __restrict__ top)
{
    __shared__ __align__(16) uint16_t Kh[64 * SR], Kl[64 * SR];
    __shared__ __align__(16) uint16_t Vh[64 * SR], Vl[64 * SR];
    __shared__ __align__(16) unsigned char Msk[64 * 64];
    __shared__ __align__(16) unsigned char Am[64];

    const int tid  = threadIdx.x;
    const int w    = tid >> 5;
    const int lane = tid & 31;
    const int gq   = lane >> 2;
    const int t4   = lane & 3;
    const int b    = blockIdx.y >> 4;
    const int h    = blockIdx.y & 15;
    const int q0   = blockIdx.x * 64;
    const int qrow = q0 + w * 16 + gq;     // this thread's rows: qrow, qrow+8

    const uint32_t kh_s = smem_u32(Kh);
    const uint32_t kl_s = smem_u32(Kl);
    const uint32_t vh_s = smem_u32(Vh);
    const uint32_t vl_s = smem_u32(Vl);

    // Q fragments (registers, held across key loop)
    uint32_t qh[4][4], ql[4][4];
    {
        const size_t qb = ((size_t)(b * L_) + qrow) * D_ + h * DH_;
        #pragma unroll
        for (int kk = 0; kk < 4; kk++) {
            qh[kk][0] = *(const uint32_t*)&qhi[qb + kk * 16 + 2 * t4];
            qh[kk][1] = *(const uint32_t*)&qhi[qb + 8 * D_ + kk * 16 + 2 * t4];
            qh[kk][2] = *(const uint32_t*)&qhi[qb + kk * 16 + 8 + 2 * t4];
            qh[kk][3] = *(const uint32_t*)&qhi[qb + 8 * D_ + kk * 16 + 8 + 2 * t4];
            ql[kk][0] = *(const uint32_t*)&qlo[qb + kk * 16 + 2 * t4];
            ql[kk][1] = *(const uint32_t*)&qlo[qb + 8 * D_ + kk * 16 + 2 * t4];
            ql[kk][2] = *(const uint32_t*)&qlo[qb + kk * 16 + 8 + 2 * t4];
            ql[kk][3] = *(const uint32_t*)&qlo[qb + 8 * D_ + kk * 16 + 8 + 2 * t4];
        }
    }

    float oacc[8][4];
    #pragma unroll
    for (int dj = 0; dj < 8; dj++)
        #pragma unroll
        for (int c = 0; c < 4; c++) oacc[dj][c] = 0.0f;
    float mrow[2] = {-1e30f, -1e30f};
    float lrow[2] = {0.0f, 0.0f};

    for (int kt = 0; kt < 16; kt++) {
        const int k0 = kt * 64;
        if (kt) __syncthreads();

        // Cooperative tile loads (K/V hi+lo, 64 rows x 64 ch)
        {
            const size_t kvb = ((size_t)(b * L_) + k0) * D_ + h * DH_;
            #pragma unroll
            for (int i = 0; i < 4; i++) {
                const int idx = tid + i * 128;        // 0..511
                const int row = idx >> 3;             // 0..63
                const int c8  = (idx & 7) * 8;        // 0..56
                const size_t src = kvb + (size_t)row * D_ + c8;
                *(uint4*)&Kh[row * SR + c8] = *(const uint4*)&khi[src];
                *(uint4*)&Kl[row * SR + c8] = *(const uint4*)&klo[src];
                *(uint4*)&Vh[row * SR + c8] = *(const uint4*)&vhi[src];
                *(uint4*)&Vl[row * SR + c8] = *(const uint4*)&vlo[src];
            }
            if (h < HG_) {
                #pragma unroll
                for (int i = 0; i < 2; i++) {
                    const int idx = tid + i * 128;    // 0..255
                    const int row = idx >> 2;
                    const int seg = (idx & 3) * 16;
                    *(uint4*)&Msk[row * 64 + seg] =
                        *(const uint4*)&mask[(size_t)b * L_ * L_ + (size_t)(q0 + row) * L_ + k0 + seg];
                }
            } else if (tid < 4) {
                *(uint4*)&Am[tid * 16] = *(const uint4*)&amask[(size_t)b * L_ + k0 + tid * 16];
            }
        }
        __syncthreads();

        // S = Q @ K^T (bf16x3)
        float sacc[8][4];
        #pragma unroll
        for (int j = 0; j < 8; j++)
            #pragma unroll
            for (int c = 0; c < 4; c++) sacc[j][c] = 0.0f;

        #pragma unroll
        for (int kk = 0; kk < 4; kk++) {
            const uint32_t coff = (uint32_t)((kk * 16 + (lane >> 4) * 8) * 2);
            #pragma unroll
            for (int jp = 0; jp < 4; jp++) {
                const uint32_t roff = (uint32_t)((jp * 16 + (lane & 15)) * SR * 2);
                uint32_t bh[4], bl[4];
                ldm4(bh, kh_s + roff + coff);
                ldm4(bl, kl_s + roff + coff);
                mma16816(sacc[2 * jp],     qh[kk], bh[0], bh[2]);
                mma16816(sacc[2 * jp + 1], qh[kk], bh[1], bh[3]);
                mma16816(sacc[2 * jp],     qh[kk], bl[0], bl[2]);
                mma16816(sacc[2 * jp + 1], qh[kk], bl[1], bl[3]);
                mma16816(sacc[2 * jp],     ql[kk], bh[0], bh[2]);
                mma16816(sacc[2 * jp + 1], ql[kk], bh[1], bh[3]);
            }
        }

        // head 0: raw scores
        if (h == 0) {
            #pragma unroll
            for (int j = 0; j < 8; j++) {
                *(float2*)&top[((size_t)(b * L_) + qrow) * L_ + k0 + j * 8 + 2 * t4] =
                    make_float2(sacc[j][0], sacc[j][1]);
                *(float2*)&top[((size_t)(b * L_) + qrow + 8) * L_ + k0 + j * 8 + 2 * t4] =
                    make_float2(sacc[j][2], sacc[j][3]);
            }
        }

        // Masking
        if (h < HG_) {
            #pragma unroll
            for (int j = 0; j < 8; j++) {
                uchar2 m0 = *(const uchar2*)&Msk[(w * 16 + gq) * 64 + j * 8 + 2 * t4];
                uchar2 m1 = *(const uchar2*)&Msk[(w * 16 + gq + 8) * 64 + j * 8 + 2 * t4];
                if (m0.x) sacc[j][0] = -1e18f;
                if (m0.y) sacc[j][1] = -1e18f;
                if (m1.x) sacc[j][2] = -1e18f;
                if (m1.y) sacc[j][3] = -1e18f;
            }
        } else {
            #pragma unroll
            for (int j = 0; j < 8; j++) {
                uchar2 m = *(const uchar2*)&Am[j * 8 + 2 * t4];
                if (m.x) { sacc[j][0] = -1e18f; sacc[j][2] = -1e18f; }
                if (m.y) { sacc[j][1] = -1e18f; sacc[j][3] = -1e18f; }
            }
        }

        // Online softmax (rows r=0: c0/c1, r=1: c2/c3)
        #pragma unroll
        for (int r = 0; r < 2; r++) {
            float mx = -1e30f;
            #pragma unroll
            for (int j = 0; j < 8; j++)
                mx = fmaxf(mx, fmaxf(sacc[j][2 * r], sacc[j][2 * r + 1]));
            mx = fmaxf(mx, __shfl_xor_sync(0xffffffffu, mx, 1));
            mx = fmaxf(mx, __shfl_xor_sync(0xffffffffu, mx, 2));
            const float mn   = fmaxf(mrow[r], mx);
            const float corr = __expf(mrow[r] - mn);
            mrow[r] = mn;
            float ps = 0.0f;
            #pragma unroll
            for (int j = 0; j < 8; j++) {
                float p0 = __expf(sacc[j][2 * r] - mn);
                float p1 = __expf(sacc[j][2 * r + 1] - mn);
                sacc[j][2 * r] = p0; sacc[j][2 * r + 1] = p1;
                ps += p0 + p1;
            }
            ps += __shfl_xor_sync(0xffffffffu, ps, 1);
            ps += __shfl_xor_sync(0xffffffffu, ps, 2);
            lrow[r] = lrow[r] * corr + ps;
            #pragma unroll
            for (int dj = 0; dj < 8; dj++) {
                oacc[dj][2 * r]     *= corr;
                oacc[dj][2 * r + 1] *= corr;
            }
        }

        // P @ V (bf16x3); V B-frags via ldmatrix.trans on row-major V
        #pragma unroll
        for (int kk = 0; kk < 4; kk++) {
            uint32_t pha[4], pla[4];
            split2(sacc[2 * kk][0],     sacc[2 * kk][1],     pha[0], pla[0]);
            split2(sacc[2 * kk][2],     sacc[2 * kk][3],     pha[1], pla[1]);
            split2(sacc[2 * kk + 1][0], sacc[2 * kk + 1][1], pha[2], pla[2]);
            split2(sacc[2 * kk + 1][2], sacc[2 * kk + 1][3], pha[3], pla[3]);

            const uint32_t vrow = (uint32_t)((kk * 16 + (lane & 15)) * SR * 2);
            #pragma unroll
            for (int dg = 0; dg < 4; dg++) {
                const uint32_t vcol = (uint32_t)((dg * 16 + (lane >> 4) * 8) * 2);
                uint32_t vh[4], vl[4];
                ldm4t(vh, vh_s + vrow + vcol);
                ldm4t(vl, vl_s + vrow + vcol);
                mma16816(oacc[2 * dg],     pha, vh[0], vh[1]);
                mma16816(oacc[2 * dg + 1], pha, vh[2], vh[3]);
                mma16816(oacc[2 * dg],     pha, vl[0], vl[1]);
                mma16816(oacc[2 * dg + 1], pha, vl[2], vl[3]);
                mma16816(oacc[2 * dg],     pla, vh[0], vh[1]);
                mma16816(oacc[2 * dg + 1], pla, vh[2], vh[3]);
            }
        }
    }

    // Epilogue: ctx = oacc / l
    const float inv0 = 1.0f / lrow[0];
    const float inv1 = 1.0f / lrow[1];
    #pragma unroll
    for (int dj = 0; dj < 8; dj++) {
        *(float2*)&ctx[((size_t)(b * L_) + qrow) * D_ + h * DH_ + dj * 8 + 2 * t4] =
            make_float2(oacc[dj][0] * inv0, oacc[dj][1] * inv0);
        *(float2*)&ctx[((size_t)(b * L_) + qrow + 8) * D_ + h * DH_ + dj * 8 + 2 * t4] =
            make_float2(oacc[dj][2] * inv1, oacc[dj][3] * inv1);
    }
}

// ---------------------------------------------------------------------------
// Launch
// ---------------------------------------------------------------------------
extern "C" void kernel_launch(void* const* d_in, const int* in_sizes, int n_in,
                              void* d_out, int out_size)
{
    const float* key   = (const float*)d_in[0];
    const float* value = (const float*)d_in[1];
    const float* query = (const float*)d_in[2];
    const void*  mask_raw  = d_in[3];
    const void*  amask_raw = d_in[4];
    const float* Wk = (const float*)d_in[5];
    const float* bk = (const float*)d_in[6];
    const float* Wv = (const float*)d_in[7];
    const float* bv = (const float*)d_in[8];
    const float* Wq = (const float*)d_in[9];
    const float* bq = (const float*)d_in[10];
    const float* Wo = (const float*)d_in[11];
    const float* bo = (const float*)d_in[12];

    float* out = (float*)d_out;
    float* top = out + (size_t)M_ * D_;

    float* ctxbuf;
    __nv_bfloat16 *khi, *klo, *vhi, *vlo, *qhi, *qlo;
    unsigned char *maskbuf, *amaskbuf;
    cudaGetSymbolAddress((void**)&ctxbuf, g_ctx);
    cudaGetSymbolAddress((void**)&khi, g_khi);
    cudaGetSymbolAddress((void**)&klo, g_klo);
    cudaGetSymbolAddress((void**)&vhi, g_vhi);
    cudaGetSymbolAddress((void**)&vlo, g_vlo);
    cudaGetSymbolAddress((void**)&qhi, g_qhi);
    cudaGetSymbolAddress((void**)&qlo, g_qlo);
    cudaGetSymbolAddress((void**)&maskbuf, g_mask);
    cudaGetSymbolAddress((void**)&amaskbuf, g_amask);

    cudaFuncSetAttribute(gemm_mma_kernel, cudaFuncAttributeMaxDynamicSharedMemorySize, GEMM_SMEM);

    // Normalize masks to uint8 (dtype auto-detected on device)
    detect_mask_dtype<<<1, 32>>>((const unsigned int*)mask_raw);
    const int nmask = B_ * L_ * L_;
    convert_mask<<<(nmask + 255) / 256, 256>>>(mask_raw, maskbuf, nmask);
    convert_mask<<<(B_ * L_ + 255) / 256, 256>>>(amask_raw, amaskbuf, B_ * L_);

    dim3 gg(D_ / 128, M_ / 128);  // (8, 64)
    gemm_mma_kernel<<<gg, 256, GEMM_SMEM>>>(key,   Wk, bk, nullptr, khi, klo, 1.0f);
    gemm_mma_kernel<<<gg, 256, GEMM_SMEM>>>(value, Wv, bv, nullptr, vhi, vlo, 1.0f);
    gemm_mma_kernel<<<gg, 256, GEMM_SMEM>>>(query, Wq, bq, nullptr, qhi, qlo, 0.125f);

    attn_tc_kernel<<<dim3(16, B_ * H_), 128>>>(qhi, qlo, khi, klo, vhi, vlo,
                                               maskbuf, amaskbuf, ctxbuf, top);

    gemm_mma_kernel<<<gg, 256, GEMM_SMEM>>>(ctxbuf, Wo, bo, out, nullptr, nullptr, 1.0f);
}